// round 12
// baseline (speedup 1.0000x reference)
#include <cuda_runtime.h>

// EM_rec_loss: fused single-kernel loss on GB300.
// R11 core + tgt loads hoisted to kernel top (with masks): removes the
// exposed load-wait at the phase-1 -> phase-2 transition. Peak live regs
// during seg-log loop: wm(28)+tgt(12)+acc(4)+ldg(4)+temps < 64 -> no spill.
//
// Inputs (metadata order):
//   d_in[0] segmentations   [8,4,7,128,128]   f32
//   d_in[1] masks           [8,4,7,128,128]   f32
//   d_in[2] reconstructions [8,4,7,3,128,128] f32
//   d_in[3] rec_tgt         [8,4,3,128,128]   f32
//   d_in[4] masks_vis       [8,4,7,128,128]   f32
//   d_in[5] attn_index      [8,4,7,7]         f32
// Output: scalar f32.

#define NB 7
#define NS 7
#define HH 128
#define WW 128
#define HW (HH * WW)        // 16384
#define HW4 (HW / 4)        // 4096 float4 groups per image plane
#define NIMG 32             // b*f
#define TPB 256
#define NWARP (TPB / 32)    // 8
#define BPN (HW4 / TPB)     // 16 blocks per image
#define GRID (NIMG * BPN)   // 512 blocks -> single wave at occ>=4

// Fixed-point scale: partials are non-negative, total*SCALE << 2^63.
#define FPSCALE 8589934592.0   // 2^33

__device__ unsigned long long g_total = 0;  // fixed-point accumulator
__device__ unsigned int      g_cnt   = 0;   // wraps to 0 every grid -> replay-safe

__device__ __forceinline__ float warp_sum(float v) {
    // Fixed butterfly order -> deterministic.
    #pragma unroll
    for (int m = 16; m > 0; m >>= 1)
        v += __shfl_xor_sync(0xFFFFFFFFu, v, m);
    return v;
}

__global__ __launch_bounds__(TPB, 4) void loss_main(
    const float* __restrict__ seg,
    const float* __restrict__ masks,
    const float* __restrict__ rec,
    const float* __restrict__ tgt,
    const float* __restrict__ mvis,
    const float* __restrict__ ai,
    float* __restrict__ out)
{
    __shared__ float s_aib[NS * NB];  // ai * (1/HW)  (BCE weight)
    __shared__ float s_aim[NS * NB];  // ai * 0.1     (MSE weight)
    __shared__ float s_asum[NB];      // sum_s ai*(1/HW)
    __shared__ float s_wred[NWARP];

    const int n = blockIdx.x / BPN;
    const int t = threadIdx.x;
    const int p4 = (blockIdx.x % BPN) * TPB + t;  // float4 index within one plane

    const float4* __restrict__ seg4 = (const float4*)seg;
    const float4* __restrict__ mk4  = (const float4*)masks;
    const float4* __restrict__ rc4  = (const float4*)rec;
    const float4* __restrict__ tg4  = (const float4*)tgt;
    const float4* __restrict__ mv4  = (const float4*)mvis;

    // Pre-issue masks (7) and tgt (3) loads BEFORE the smem preamble: they
    // depend only on p4/n, and LDGs issued before BAR.SYNC stay in flight
    // across it, hiding the ai-gather latency, both barriers, and the
    // phase-2 tgt wait under bulk traffic.
    float4 mkr[NS];
    #pragma unroll
    for (int s = 0; s < NS; s++)
        mkr[s] = mk4[(size_t)(n * NS + s) * HW4 + p4];
    const float4 t0 = tg4[((size_t)n * 3 + 0) * HW4 + p4];
    const float4 t1 = tg4[((size_t)n * 3 + 1) * HW4 + p4];
    const float4 t2 = tg4[((size_t)n * 3 + 2) * HW4 + p4];

    if (t < NS * NB) {
        float a = ai[n * NS * NB + t];
        s_aib[t] = a * (1.0f / (float)HW);
        s_aim[t] = a * 0.1f;
    }
    __syncthreads();
    if (t < NB) {
        float s = 0.0f;
        #pragma unroll
        for (int j = 0; j < NS; j++) s += s_aib[j * NB + t];
        s_asum[t] = s;
    }
    __syncthreads();

    float acc[4] = { 0.0f, 0.0f, 0.0f, 0.0f };

    // ================= Phase 1: BCE (masks -> wm, then seg logs) =============
    {
        float wm[NB][4];
        #pragma unroll
        for (int b = 0; b < NB; b++)
            #pragma unroll
            for (int c = 0; c < 4; c++) wm[b][c] = 0.0f;

        #pragma unroll
        for (int s = 0; s < NS; s++) {
            float4 mk = mkr[s];   // already in flight / landed
            float mb[4] = { mk.x > 0.5f ? 1.0f : 0.0f, mk.y > 0.5f ? 1.0f : 0.0f,
                            mk.z > 0.5f ? 1.0f : 0.0f, mk.w > 0.5f ? 1.0f : 0.0f };
            #pragma unroll
            for (int b = 0; b < NB; b++) {
                float ab = s_aib[s * NB + b];
                #pragma unroll
                for (int c = 0; c < 4; c++)
                    wm[b][c] = fmaf(mb[c], ab, wm[b][c]);
            }
        }

        #pragma unroll
        for (int b = 0; b < NB; b++) {
            float4 sg = seg4[(size_t)(n * NB + b) * HW4 + p4];
            float sv[4] = { sg.x, sg.y, sg.z, sg.w };
            float asb = s_asum[b];
            #pragma unroll
            for (int c = 0; c < 4; c++) {
                // Inputs are in (1e-4, 1-1e-4): logs are in [-9.3, 0), so the
                // reference's clamp-at--100 is a provable no-op here.
                float lp  = __logf(sv[c]);
                float l1p = __logf(1.0f - sv[c]);
                acc[c] = fmaf(-l1p, asb, acc[c]);
                acc[c] = fmaf(l1p - lp, wm[b][c], acc[c]);
            }
        }
    }

    // ================= Phase 2: MSE (mvis -> wmv, then rec/tgt) ==============
    {
        float wmv[NB][4];
        #pragma unroll
        for (int b = 0; b < NB; b++)
            #pragma unroll
            for (int c = 0; c < 4; c++) wmv[b][c] = 0.0f;

        #pragma unroll
        for (int s = 0; s < NS; s++) {
            float4 mv = mv4[(size_t)(n * NS + s) * HW4 + p4];
            float vb[4] = { mv.x > 0.5f ? 1.0f : 0.0f, mv.y > 0.5f ? 1.0f : 0.0f,
                            mv.z > 0.5f ? 1.0f : 0.0f, mv.w > 0.5f ? 1.0f : 0.0f };
            #pragma unroll
            for (int b = 0; b < NB; b++) {
                float am = s_aim[s * NB + b];
                #pragma unroll
                for (int c = 0; c < 4; c++)
                    wmv[b][c] = fmaf(vb[c], am, wmv[b][c]);
            }
        }

        const float tv0[4] = { t0.x, t0.y, t0.z, t0.w };
        const float tv1[4] = { t1.x, t1.y, t1.z, t1.w };
        const float tv2[4] = { t2.x, t2.y, t2.z, t2.w };

        #pragma unroll
        for (int b = 0; b < NB; b++) {
            float4 r0 = rc4[((size_t)(n * NB + b) * 3 + 0) * HW4 + p4];
            float4 r1 = rc4[((size_t)(n * NB + b) * 3 + 1) * HW4 + p4];
            float4 r2 = rc4[((size_t)(n * NB + b) * 3 + 2) * HW4 + p4];
            float rv0[4] = { r0.x, r0.y, r0.z, r0.w };
            float rv1[4] = { r1.x, r1.y, r1.z, r1.w };
            float rv2[4] = { r2.x, r2.y, r2.z, r2.w };
            #pragma unroll
            for (int c = 0; c < 4; c++) {
                float d0 = rv0[c] - tv0[c];
                float d1 = rv1[c] - tv1[c];
                float d2 = rv2[c] - tv2[c];
                float e = fmaf(d0, d0, fmaf(d1, d1, d2 * d2));
                acc[c] = fmaf(e, wmv[b][c], acc[c]);
            }
        }
    }

    float total = (acc[0] + acc[1]) + (acc[2] + acc[3]);

    // Deterministic block reduction: warp shuffle + tiny smem stage.
    total = warp_sum(total);
    const int lane = t & 31;
    const int warp = t >> 5;
    if (lane == 0) s_wred[warp] = total;
    __syncthreads();
    if (warp == 0) {
        float v = (lane < NWARP) ? s_wred[lane] : 0.0f;
        #pragma unroll
        for (int m = NWARP / 2; m > 0; m >>= 1)
            v += __shfl_xor_sync(0xFFFFFFFFu, v, m);
        if (lane == 0) {
            // Fixed-point contribution: integer add is associative ->
            // bitwise deterministic under any arrival order.
            unsigned long long q =
                (unsigned long long)__double2ll_rn((double)v * FPSCALE);
            atomicAdd(&g_total, q);
            __threadfence();
            unsigned int old = atomicInc(&g_cnt, GRID - 1);  // wraps -> replay-safe
            if (old == GRID - 1) {
                // Last arriver: read grand total AND reset for next replay.
                unsigned long long tot = atomicExch(&g_total, 0ULL);
                // final scale: LOSS_WEIGHT / (b*f*ns*nb) = 20 / 1568
                out[0] = (float)((double)tot * (1.0 / FPSCALE) * (20.0 / 1568.0));
            }
        }
    }
}

extern "C" void kernel_launch(void* const* d_in, const int* in_sizes, int n_in,
                              void* d_out, int out_size)
{
    (void)in_sizes; (void)n_in; (void)out_size;
    const float* seg  = (const float*)d_in[0];
    const float* mks  = (const float*)d_in[1];
    const float* rec  = (const float*)d_in[2];
    const float* tgt  = (const float*)d_in[3];
    const float* mvis = (const float*)d_in[4];
    const float* ai   = (const float*)d_in[5];
    float* out = (float*)d_out;

    loss_main<<<GRID, TPB>>>(seg, mks, rec, tgt, mvis, ai, out);
}